// round 5
// baseline (speedup 1.0000x reference)
#include <cuda_runtime.h>
#include <cstddef>
#include <cstdint>

#define Bc 48
#define Wn 8192
#define Fc 64
#define Dc 128
#define GRAM_CHUNKS 32

typedef unsigned long long ull;

// device scratch (no runtime allocation allowed)
__device__ float g_gram_part[Bc * GRAM_CHUNKS * Fc * Fc];
__device__ float g_gram[Bc * Fc * Fc];
__device__ float g_h[(size_t)Bc * Wn * Fc];     // 100.7 MB intermediate
__device__ float g_cwt[192 * 64];               // ctx_w transposed  [g*3+k][f]
__device__ float g_twr[192 * 128];              // token_w transposed [f*3+k][d]

// ---------------------------------------------------------------------------
// packed f32x2 helpers
// ---------------------------------------------------------------------------
__device__ __forceinline__ ull pack2(float a, float b) {
    ull r;
    asm("mov.b64 %0, {%1, %2};" : "=l"(r) : "r"(__float_as_uint(a)), "r"(__float_as_uint(b)));
    return r;
}
__device__ __forceinline__ ull dup2(float a) {
    ull r;
    asm("mov.b64 %0, {%1, %1};" : "=l"(r) : "r"(__float_as_uint(a)));
    return r;
}
__device__ __forceinline__ void unpack2(ull v, float& a, float& b) {
    unsigned lo, hi;
    asm("mov.b64 {%0, %1}, %2;" : "=r"(lo), "=r"(hi) : "l"(v));
    a = __uint_as_float(lo); b = __uint_as_float(hi);
}
__device__ __forceinline__ ull ffma2(ull a, ull b, ull c) {
    ull d;
    asm("fma.rn.f32x2 %0, %1, %2, %3;" : "=l"(d) : "l"(a), "l"(b), "l"(c));
    return d;
}
__device__ __forceinline__ void lds128p(unsigned addr, ull& a, ull& b) {
    asm volatile("ld.shared.v2.u64 {%0, %1}, [%2];" : "=l"(a), "=l"(b) : "r"(addr));
}

// ---------------------------------------------------------------------------
// Kernel 0: one-time weight transposes (tiny)
// ---------------------------------------------------------------------------
__global__ void __launch_bounds__(256) transpose_weights(
    const float* __restrict__ ctx_w, const float* __restrict__ token_w) {
    int tid = blockIdx.x * 256 + threadIdx.x;
    int nt = gridDim.x * 256;
    for (int i = tid; i < 64 * 192; i += nt) {
        int jj = i >> 6, f = i & 63;
        g_cwt[jj * 64 + f] = ctx_w[f * 192 + jj];
    }
    for (int i = tid; i < 128 * 192; i += nt) {
        int jj = i >> 7, d = i & 127;
        g_twr[jj * 128 + d] = token_w[d * 192 + jj];
    }
}

// ---------------------------------------------------------------------------
// Kernel 1: per-chunk partial Gram (FFMA2, parallel norm). Unchanged from R4.
// ---------------------------------------------------------------------------
__global__ void __launch_bounds__(256) gram_partial(const float* __restrict__ x) {
    const int b = blockIdx.y;
    const int chunk = blockIdx.x;
    const int w_base = chunk * (Wn / GRAM_CHUNKS);

    __shared__ float xs[64][66];
    __shared__ float npart[4][64];
    __shared__ float sinv2[64];

    const int t = threadIdx.x;
    const int ti = t >> 4;
    const int tj = t & 15;

    ull acc[4][2];
    #pragma unroll
    for (int a = 0; a < 4; a++) { acc[a][0] = 0ull; acc[a][1] = 0ull; }

    const float* xb = x + (size_t)b * Wn * Fc;

    for (int tile = 0; tile < 256; tile += 64) {
        for (int i = t; i < 64 * 64; i += 256) {
            int r = i >> 6, c = i & 63;
            xs[r][c] = xb[(size_t)(w_base + tile + r) * Fc + c];
        }
        __syncthreads();
        {
            int q = t >> 6, r = t & 63;
            float s = 0.f;
            #pragma unroll
            for (int c = 0; c < 16; c++) { float v = xs[r][q * 16 + c]; s += v * v; }
            npart[q][r] = s;
        }
        __syncthreads();
        if (t < 64)
            sinv2[t] = 1.0f / (npart[0][t] + npart[1][t] + npart[2][t] + npart[3][t]);
        __syncthreads();

        #pragma unroll 4
        for (int w = 0; w < 64; w++) {
            float s = sinv2[w];
            const ull* row = (const ull*)(&xs[w][0]);
            ull vj0 = row[tj], vj1 = row[tj + 16];
            float vi0 = xs[w][ti] * s,      vi1 = xs[w][ti + 16] * s;
            float vi2 = xs[w][ti + 32] * s, vi3 = xs[w][ti + 48] * s;
            acc[0][0] = ffma2(dup2(vi0), vj0, acc[0][0]);
            acc[0][1] = ffma2(dup2(vi0), vj1, acc[0][1]);
            acc[1][0] = ffma2(dup2(vi1), vj0, acc[1][0]);
            acc[1][1] = ffma2(dup2(vi1), vj1, acc[1][1]);
            acc[2][0] = ffma2(dup2(vi2), vj0, acc[2][0]);
            acc[2][1] = ffma2(dup2(vi2), vj1, acc[2][1]);
            acc[3][0] = ffma2(dup2(vi3), vj0, acc[3][0]);
            acc[3][1] = ffma2(dup2(vi3), vj1, acc[3][1]);
        }
        __syncthreads();
    }

    float* dst = g_gram_part + ((size_t)b * GRAM_CHUNKS + chunk) * (Fc * Fc);
    #pragma unroll
    for (int a = 0; a < 4; a++)
        #pragma unroll
        for (int c = 0; c < 2; c++) {
            float u, v;
            unpack2(acc[a][c], u, v);
            *(float2*)(dst + (ti + 16 * a) * 64 + 2 * (tj + 16 * c)) = make_float2(u, v);
        }
}

__global__ void __launch_bounds__(256) gram_reduce() {
    const int b = blockIdx.x;
    const int t = threadIdx.x;
    for (int i = t; i < Fc * Fc; i += 256) {
        float s = 0.f;
        #pragma unroll
        for (int c = 0; c < GRAM_CHUNKS; c++)
            s += g_gram_part[((size_t)b * GRAM_CHUNKS + c) * (Fc * Fc) + i];
        g_gram[b * Fc * Fc + i] = s;
    }
}

// ---------------------------------------------------------------------------
// Kernel H: h = ctxConv(x)+ctx_b + relu(gram@seW + seb)
// CTA = 256 w x 64 f, 1024 threads = 64 wgroups (T_w=4) x 16 fgroups (T_f=2 pairs)
// -> 32 warps/SM. Two passes over g sharing one accumulator set.
// ---------------------------------------------------------------------------
#define H_CWT  0                         // 12288
#define H_GRAM 12288                     // 4096
#define XSTR   260
#define H_XT   16384                     // 64*260 (x_t[g][j], j=0..257)
#define SSTR   258
#define H_SEWT 33024                     // 64*258 (sew_t[g][r], r=0..255)
#define H_TOTALF 49536
#define H_SMEM (H_TOTALF * 4)            // 198144 B

__global__ void __launch_bounds__(1024, 1) h_kernel(
    const float* __restrict__ x,
    const float* __restrict__ ctx_b,
    const float* __restrict__ seW_w,
    const float* __restrict__ seW_b)
{
    extern __shared__ float sm[];
    const int b  = blockIdx.y;
    const int w0 = blockIdx.x * 256;
    const int t  = threadIdx.x;
    const float* xb = x + (size_t)b * Wn * Fc;

    // ---- staging ----
    for (int i = t; i < 192 * 64; i += 1024) sm[H_CWT + i] = g_cwt[i];
    for (int i = t; i < 4096; i += 1024)     sm[H_GRAM + i] = g_gram[b * 4096 + i];
    for (int i = t; i < 258 * 64; i += 1024) {
        int j = i >> 6, c = i & 63;
        int gr = w0 - 1 + j;
        sm[H_XT + c * XSTR + j] = (gr >= 0 && gr < Wn) ? xb[(size_t)gr * Fc + c] : 0.f;
    }
    for (int i = t; i < 256 * 64; i += 1024) {
        int r = i >> 6, c = i & 63;
        sm[H_SEWT + c * SSTR + r] = seW_w[(size_t)(w0 + r) * Fc + c];
    }
    __syncthreads();

    const int fg = t & 15;         // f0 = fg*4 (2 pairs)
    const int wq = t >> 4;         // 0..63, wbase = wq*4
    const int f0 = fg * 4;
    const int wbase = wq * 4;

    ull acc[4][2];
    #pragma unroll
    for (int r = 0; r < 4; r++) { acc[r][0] = 0ull; acc[r][1] = 0ull; }

    unsigned sbase = (unsigned)__cvta_generic_to_shared(sm);

    // ======== pass 1: SE = gram @ seW ========
    {
        unsigned gr_a = sbase + (H_GRAM + f0) * 4;
        const float2* sp = (const float2*)(sm + H_SEWT + wbase);
        #pragma unroll 4
        for (int g = 0; g < 64; g++) {
            ull gA, gB;
            lds128p(gr_a, gA, gB);
            gr_a += 256;
            float2 s01 = sp[0], s23 = sp[1];
            sp += SSTR / 2;
            ull d0 = dup2(s01.x), d1 = dup2(s01.y), d2 = dup2(s23.x), d3 = dup2(s23.y);
            acc[0][0] = ffma2(d0, gA, acc[0][0]); acc[0][1] = ffma2(d0, gB, acc[0][1]);
            acc[1][0] = ffma2(d1, gA, acc[1][0]); acc[1][1] = ffma2(d1, gB, acc[1][1]);
            acc[2][0] = ffma2(d2, gA, acc[2][0]); acc[2][1] = ffma2(d2, gB, acc[2][1]);
            acc[3][0] = ffma2(d3, gA, acc[3][0]); acc[3][1] = ffma2(d3, gB, acc[3][1]);
        }
    }

    // ======== relu + fold biases into acc ========
    {
        float cb0 = __ldg(ctx_b + f0),     cb1 = __ldg(ctx_b + f0 + 1);
        float cb2 = __ldg(ctx_b + f0 + 2), cb3 = __ldg(ctx_b + f0 + 3);
        #pragma unroll
        for (int r = 0; r < 4; r++) {
            float seb = __ldg(seW_b + w0 + wbase + r);
            float u, v;
            unpack2(acc[r][0], u, v);
            acc[r][0] = pack2(fmaxf(u + seb, 0.f) + cb0, fmaxf(v + seb, 0.f) + cb1);
            unpack2(acc[r][1], u, v);
            acc[r][1] = pack2(fmaxf(u + seb, 0.f) + cb2, fmaxf(v + seb, 0.f) + cb3);
        }
    }

    // ======== pass 2: += contextConv ========
    {
        unsigned cwt_a = sbase + (H_CWT + f0) * 4;
        const float2* xp = (const float2*)(sm + H_XT + wbase);
        #pragma unroll 2
        for (int g = 0; g < 64; g++) {
            float2 p0 = xp[0], p1 = xp[1], p2 = xp[2];
            xp += XSTR / 2;
            ull xd[6];
            xd[0] = dup2(p0.x); xd[1] = dup2(p0.y);
            xd[2] = dup2(p1.x); xd[3] = dup2(p1.y);
            xd[4] = dup2(p2.x); xd[5] = dup2(p2.y);
            #pragma unroll
            for (int k = 0; k < 3; k++) {
                ull wA, wB;
                lds128p(cwt_a + (unsigned)k * 256, wA, wB);
                #pragma unroll
                for (int r = 0; r < 4; r++) {
                    acc[r][0] = ffma2(xd[r + k], wA, acc[r][0]);
                    acc[r][1] = ffma2(xd[r + k], wB, acc[r][1]);
                }
            }
            cwt_a += 768;
        }
    }

    // ---- store ----
    #pragma unroll
    for (int r = 0; r < 4; r++) {
        float o0, o1, o2, o3;
        unpack2(acc[r][0], o0, o1);
        unpack2(acc[r][1], o2, o3);
        *(float4*)(g_h + ((size_t)b * Wn + w0 + wbase + r) * Fc + f0) =
            make_float4(o0, o1, o2, o3);
    }
}

// ---------------------------------------------------------------------------
// Kernel O: out[b,w,d] = sum_{f,k} h[b,(w+k-1)%Wn,f] * token_w[d,f,k]
// CTA = 256 w x 128 d, 1024 threads = 64 wgroups (T_w=4) x 16 dgroups
// (T_d=4 pairs) -> 32 warps/SM.
// ---------------------------------------------------------------------------
#define O_TWR 0                          // 24576
#define HSTR  260
#define O_HT  24576                      // 64*260 (h_t[f][j], j=0..257)
#define O_TOTALF 41216
#define O_SMEM (O_TOTALF * 4)            // 164864 B

__global__ void __launch_bounds__(1024, 1) out_kernel(float* __restrict__ out)
{
    extern __shared__ float sm[];
    const int b  = blockIdx.y;
    const int w0 = blockIdx.x * 256;
    const int t  = threadIdx.x;

    for (int i = t; i < 192 * 128; i += 1024) sm[O_TWR + i] = g_twr[i];
    const float* hg = g_h + (size_t)b * Wn * Fc;
    for (int i = t; i < 258 * 64; i += 1024) {
        int j = i >> 6, c = i & 63;
        int gw = (w0 - 1 + j + Wn) & (Wn - 1);
        sm[O_HT + c * HSTR + j] = hg[(size_t)gw * Fc + c];
    }
    __syncthreads();

    const int dg = t & 15;         // d0 = dg*8 (4 pairs)
    const int wq = t >> 4;         // 0..63, wbase = wq*4
    const int d0 = dg * 8;
    const int wbase = wq * 4;

    ull acc[4][4];
    #pragma unroll
    for (int r = 0; r < 4; r++)
        #pragma unroll
        for (int p = 0; p < 4; p++) acc[r][p] = 0ull;

    unsigned sbase = (unsigned)__cvta_generic_to_shared(sm);
    unsigned twr_a = sbase + (O_TWR + d0) * 4;
    const float2* hp = (const float2*)(sm + O_HT + wbase);

    #pragma unroll 2
    for (int f = 0; f < 64; f++) {
        float2 p0 = hp[0], p1 = hp[1], p2 = hp[2];
        hp += HSTR / 2;
        ull hd[6];
        hd[0] = dup2(p0.x); hd[1] = dup2(p0.y);
        hd[2] = dup2(p1.x); hd[3] = dup2(p1.y);
        hd[4] = dup2(p2.x); hd[5] = dup2(p2.y);
        #pragma unroll
        for (int k = 0; k < 3; k++) {
            ull wA, wB, wC, wD;
            unsigned a = twr_a + (unsigned)k * 512;
            lds128p(a, wA, wB);
            lds128p(a + 16, wC, wD);
            #pragma unroll
            for (int r = 0; r < 4; r++) {
                acc[r][0] = ffma2(hd[r + k], wA, acc[r][0]);
                acc[r][1] = ffma2(hd[r + k], wB, acc[r][1]);
                acc[r][2] = ffma2(hd[r + k], wC, acc[r][2]);
                acc[r][3] = ffma2(hd[r + k], wD, acc[r][3]);
            }
        }
        twr_a += 1536;
    }

    #pragma unroll
    for (int r = 0; r < 4; r++) {
        float a0, a1, a2, a3, a4, a5, a6, a7;
        unpack2(acc[r][0], a0, a1);
        unpack2(acc[r][1], a2, a3);
        unpack2(acc[r][2], a4, a5);
        unpack2(acc[r][3], a6, a7);
        float* ob = out + ((size_t)b * Wn + w0 + wbase + r) * Dc + d0;
        *(float4*)(ob)     = make_float4(a0, a1, a2, a3);
        *(float4*)(ob + 4) = make_float4(a4, a5, a6, a7);
    }
}

// ---------------------------------------------------------------------------
extern "C" void kernel_launch(void* const* d_in, const int* in_sizes, int n_in,
                              void* d_out, int out_size) {
    const float* x       = (const float*)d_in[0];
    const float* ctx_w   = (const float*)d_in[1];
    const float* ctx_b   = (const float*)d_in[2];
    const float* token_w = (const float*)d_in[3];
    const float* seW_w   = (const float*)d_in[4];
    const float* seW_b   = (const float*)d_in[5];
    float* out = (float*)d_out;

    cudaFuncSetAttribute(h_kernel,
                         cudaFuncAttributeMaxDynamicSharedMemorySize, H_SMEM);
    cudaFuncSetAttribute(out_kernel,
                         cudaFuncAttributeMaxDynamicSharedMemorySize, O_SMEM);

    transpose_weights<<<48, 256>>>(ctx_w, token_w);
    gram_partial<<<dim3(GRAM_CHUNKS, Bc), 256>>>(x);
    gram_reduce<<<Bc, 256>>>();
    h_kernel<<<dim3(Wn / 256, Bc), 1024, H_SMEM>>>(x, ctx_b, seW_w, seW_b);
    out_kernel<<<dim3(Wn / 256, Bc), 1024, O_SMEM>>>(out);
}

// round 7
// speedup vs baseline: 1.5050x; 1.5050x over previous
#include <cuda_runtime.h>
#include <cstddef>
#include <cstdint>

#define Bc 48
#define Wn 8192
#define Fc 64
#define Dc 128
#define GRAM_CHUNKS 32

typedef unsigned long long ull;

// device scratch (no runtime allocation allowed)
__device__ float g_gram_part[Bc * GRAM_CHUNKS * Fc * Fc];
__device__ float g_gram[Bc * Fc * Fc];
__device__ float g_h[(size_t)Bc * Wn * Fc];     // 100.7 MB intermediate
__device__ float g_cwt[192 * 64];               // ctx_w transposed  [g*3+k][f]
__device__ float g_twB[128 * 192];              // token_w reordered [d][k*64+f]

// ---------------------------------------------------------------------------
// packed f32x2 helpers
// ---------------------------------------------------------------------------
__device__ __forceinline__ ull pack2(float a, float b) {
    ull r;
    asm("mov.b64 %0, {%1, %2};" : "=l"(r) : "r"(__float_as_uint(a)), "r"(__float_as_uint(b)));
    return r;
}
__device__ __forceinline__ ull dup2(float a) {
    ull r;
    asm("mov.b64 %0, {%1, %1};" : "=l"(r) : "r"(__float_as_uint(a)));
    return r;
}
__device__ __forceinline__ void unpack2(ull v, float& a, float& b) {
    unsigned lo, hi;
    asm("mov.b64 {%0, %1}, %2;" : "=r"(lo), "=r"(hi) : "l"(v));
    a = __uint_as_float(lo); b = __uint_as_float(hi);
}
__device__ __forceinline__ ull ffma2(ull a, ull b, ull c) {
    ull d;
    asm("fma.rn.f32x2 %0, %1, %2, %3;" : "=l"(d) : "l"(a), "l"(b), "l"(c));
    return d;
}
__device__ __forceinline__ void lds128p(unsigned addr, ull& a, ull& b) {
    asm volatile("ld.shared.v2.u64 {%0, %1}, [%2];" : "=l"(a), "=l"(b) : "r"(addr));
}

// ---------------------------------------------------------------------------
// tensor-core helpers (legacy mma.sync path — compiles under compute_103)
// ---------------------------------------------------------------------------
__device__ __forceinline__ uint32_t smem_u32(const void* p) {
    uint32_t a;
    asm("{ .reg .u64 t; cvta.to.shared.u64 t, %1; cvt.u32.u64 %0, t; }" : "=r"(a) : "l"(p));
    return a;
}
__device__ __forceinline__ uint32_t cvt_tf32(float x) {
    uint32_t r;
    asm("cvt.rna.tf32.f32 %0, %1;" : "=r"(r) : "f"(x));
    return r;
}
__device__ __forceinline__ void ldsm_x4(uint32_t addr, uint32_t* r) {
    asm volatile("ldmatrix.sync.aligned.m8n8.x4.shared.b16 {%0,%1,%2,%3}, [%4];"
                 : "=r"(r[0]), "=r"(r[1]), "=r"(r[2]), "=r"(r[3]) : "r"(addr));
}
__device__ __forceinline__ void mma_tf32(float* c, const uint32_t* a,
                                         uint32_t b0, uint32_t b1) {
    asm volatile(
        "mma.sync.aligned.m16n8k8.row.col.f32.tf32.tf32.f32 "
        "{%0,%1,%2,%3}, {%4,%5,%6,%7}, {%8,%9}, {%0,%1,%2,%3};"
        : "+f"(c[0]), "+f"(c[1]), "+f"(c[2]), "+f"(c[3])
        : "r"(a[0]), "r"(a[1]), "r"(a[2]), "r"(a[3]), "r"(b0), "r"(b1));
}

// ---------------------------------------------------------------------------
// Kernel 0: one-time weight reorders (tiny)
// ---------------------------------------------------------------------------
__global__ void __launch_bounds__(256) transpose_weights(
    const float* __restrict__ ctx_w, const float* __restrict__ token_w) {
    int tid = blockIdx.x * 256 + threadIdx.x;
    int nt = gridDim.x * 256;
    for (int i = tid; i < 64 * 192; i += nt) {
        int jj = i >> 6, f = i & 63;
        g_cwt[jj * 64 + f] = ctx_w[f * 192 + jj];
    }
    // g_twB[d][k*64+f] = token_w[d][f*3+k]
    for (int i = tid; i < 128 * 192; i += nt) {
        int d = i / 192, j = i - d * 192;
        int k = j >> 6, f = j & 63;
        g_twB[i] = token_w[d * 192 + f * 3 + k];
    }
}

// ---------------------------------------------------------------------------
// Kernel 1: per-chunk partial Gram (FFMA2, parallel norm). R4 version.
// ---------------------------------------------------------------------------
__global__ void __launch_bounds__(256) gram_partial(const float* __restrict__ x) {
    const int b = blockIdx.y;
    const int chunk = blockIdx.x;
    const int w_base = chunk * (Wn / GRAM_CHUNKS);

    __shared__ float xs[64][66];
    __shared__ float npart[4][64];
    __shared__ float sinv2[64];

    const int t = threadIdx.x;
    const int ti = t >> 4;
    const int tj = t & 15;

    ull acc[4][2];
    #pragma unroll
    for (int a = 0; a < 4; a++) { acc[a][0] = 0ull; acc[a][1] = 0ull; }

    const float* xb = x + (size_t)b * Wn * Fc;

    for (int tile = 0; tile < 256; tile += 64) {
        for (int i = t; i < 64 * 64; i += 256) {
            int r = i >> 6, c = i & 63;
            xs[r][c] = xb[(size_t)(w_base + tile + r) * Fc + c];
        }
        __syncthreads();
        {
            int q = t >> 6, r = t & 63;
            float s = 0.f;
            #pragma unroll
            for (int c = 0; c < 16; c++) { float v = xs[r][q * 16 + c]; s += v * v; }
            npart[q][r] = s;
        }
        __syncthreads();
        if (t < 64)
            sinv2[t] = 1.0f / (npart[0][t] + npart[1][t] + npart[2][t] + npart[3][t]);
        __syncthreads();

        #pragma unroll 4
        for (int w = 0; w < 64; w++) {
            float s = sinv2[w];
            const ull* row = (const ull*)(&xs[w][0]);
            ull vj0 = row[tj], vj1 = row[tj + 16];
            float vi0 = xs[w][ti] * s,      vi1 = xs[w][ti + 16] * s;
            float vi2 = xs[w][ti + 32] * s, vi3 = xs[w][ti + 48] * s;
            acc[0][0] = ffma2(dup2(vi0), vj0, acc[0][0]);
            acc[0][1] = ffma2(dup2(vi0), vj1, acc[0][1]);
            acc[1][0] = ffma2(dup2(vi1), vj0, acc[1][0]);
            acc[1][1] = ffma2(dup2(vi1), vj1, acc[1][1]);
            acc[2][0] = ffma2(dup2(vi2), vj0, acc[2][0]);
            acc[2][1] = ffma2(dup2(vi2), vj1, acc[2][1]);
            acc[3][0] = ffma2(dup2(vi3), vj0, acc[3][0]);
            acc[3][1] = ffma2(dup2(vi3), vj1, acc[3][1]);
        }
        __syncthreads();
    }

    float* dst = g_gram_part + ((size_t)b * GRAM_CHUNKS + chunk) * (Fc * Fc);
    #pragma unroll
    for (int a = 0; a < 4; a++)
        #pragma unroll
        for (int c = 0; c < 2; c++) {
            float u, v;
            unpack2(acc[a][c], u, v);
            *(float2*)(dst + (ti + 16 * a) * 64 + 2 * (tj + 16 * c)) = make_float2(u, v);
        }
}

__global__ void __launch_bounds__(256) gram_reduce() {
    const int b = blockIdx.x;
    const int t = threadIdx.x;
    for (int i = t; i < Fc * Fc; i += 256) {
        float s = 0.f;
        #pragma unroll
        for (int c = 0; c < GRAM_CHUNKS; c++)
            s += g_gram_part[((size_t)b * GRAM_CHUNKS + c) * (Fc * Fc) + i];
        g_gram[b * Fc * Fc + i] = s;
    }
}

// ---------------------------------------------------------------------------
// Kernel H: h = ctxConv(x)+ctx_b + relu(gram@seW + seb)  — R4 winner config.
// ---------------------------------------------------------------------------
#define H_CWT  0
#define H_GRAM 12288
#define XSTR   260
#define H_XT   16384
#define SSTR   258
#define H_SEWT 33024
#define H_TOTALF 49536
#define H_SMEM (H_TOTALF * 4)

__global__ void __launch_bounds__(512, 1) h_kernel(
    const float* __restrict__ x,
    const float* __restrict__ ctx_b,
    const float* __restrict__ seW_w,
    const float* __restrict__ seW_b)
{
    extern __shared__ float sm[];
    const int b  = blockIdx.y;
    const int w0 = blockIdx.x * 256;
    const int t  = threadIdx.x;
    const float* xb = x + (size_t)b * Wn * Fc;

    for (int i = t; i < 192 * 64; i += 512) sm[H_CWT + i] = g_cwt[i];
    for (int i = t; i < 4096; i += 512)     sm[H_GRAM + i] = g_gram[b * 4096 + i];
    for (int i = t; i < 258 * 64; i += 512) {
        int j = i >> 6, c = i & 63;
        int gr = w0 - 1 + j;
        sm[H_XT + c * XSTR + j] = (gr >= 0 && gr < Wn) ? xb[(size_t)gr * Fc + c] : 0.f;
    }
    for (int i = t; i < 256 * 64; i += 512) {
        int r = i >> 6, c = i & 63;
        sm[H_SEWT + c * SSTR + r] = seW_w[(size_t)(w0 + r) * Fc + c];
    }
    __syncthreads();

    const int fg = t & 15;
    const int wq = t >> 4;
    const int f0 = fg * 4;
    const int wbase = wq * 8;

    ull acc[8][2];
    #pragma unroll
    for (int r = 0; r < 8; r++) { acc[r][0] = 0ull; acc[r][1] = 0ull; }

    unsigned sbase = smem_u32(sm);

    // pass 1: SE = gram @ seW
    {
        unsigned gr_a = sbase + (H_GRAM + f0) * 4;
        const float2* sp = (const float2*)(sm + H_SEWT + wbase);
        #pragma unroll 2
        for (int g = 0; g < 64; g++) {
            ull gA, gB;
            lds128p(gr_a, gA, gB);
            gr_a += 256;
            float2 s01 = sp[0], s23 = sp[1], s45 = sp[2], s67 = sp[3];
            sp += SSTR / 2;
            ull d0 = dup2(s01.x), d1 = dup2(s01.y), d2 = dup2(s23.x), d3 = dup2(s23.y);
            ull d4 = dup2(s45.x), d5 = dup2(s45.y), d6 = dup2(s67.x), d7 = dup2(s67.y);
            acc[0][0] = ffma2(d0, gA, acc[0][0]); acc[0][1] = ffma2(d0, gB, acc[0][1]);
            acc[1][0] = ffma2(d1, gA, acc[1][0]); acc[1][1] = ffma2(d1, gB, acc[1][1]);
            acc[2][0] = ffma2(d2, gA, acc[2][0]); acc[2][1] = ffma2(d2, gB, acc[2][1]);
            acc[3][0] = ffma2(d3, gA, acc[3][0]); acc[3][1] = ffma2(d3, gB, acc[3][1]);
            acc[4][0] = ffma2(d4, gA, acc[4][0]); acc[4][1] = ffma2(d4, gB, acc[4][1]);
            acc[5][0] = ffma2(d5, gA, acc[5][0]); acc[5][1] = ffma2(d5, gB, acc[5][1]);
            acc[6][0] = ffma2(d6, gA, acc[6][0]); acc[6][1] = ffma2(d6, gB, acc[6][1]);
            acc[7][0] = ffma2(d7, gA, acc[7][0]); acc[7][1] = ffma2(d7, gB, acc[7][1]);
        }
    }

    // relu + fold biases
    {
        float cb0 = __ldg(ctx_b + f0),     cb1 = __ldg(ctx_b + f0 + 1);
        float cb2 = __ldg(ctx_b + f0 + 2), cb3 = __ldg(ctx_b + f0 + 3);
        #pragma unroll
        for (int r = 0; r < 8; r++) {
            float seb = __ldg(seW_b + w0 + wbase + r);
            float u, v;
            unpack2(acc[r][0], u, v);
            acc[r][0] = pack2(fmaxf(u + seb, 0.f) + cb0, fmaxf(v + seb, 0.f) + cb1);
            unpack2(acc[r][1], u, v);
            acc[r][1] = pack2(fmaxf(u + seb, 0.f) + cb2, fmaxf(v + seb, 0.f) + cb3);
        }
    }

    // pass 2: += contextConv
    {
        unsigned cwt_a = sbase + (H_CWT + f0) * 4;
        const float2* xp = (const float2*)(sm + H_XT + wbase);
        #pragma unroll 2
        for (int g = 0; g < 64; g++) {
            float2 p0 = xp[0], p1 = xp[1], p2 = xp[2], p3 = xp[3], p4 = xp[4];
            xp += XSTR / 2;
            ull xd[10];
            xd[0] = dup2(p0.x); xd[1] = dup2(p0.y);
            xd[2] = dup2(p1.x); xd[3] = dup2(p1.y);
            xd[4] = dup2(p2.x); xd[5] = dup2(p2.y);
            xd[6] = dup2(p3.x); xd[7] = dup2(p3.y);
            xd[8] = dup2(p4.x); xd[9] = dup2(p4.y);
            #pragma unroll
            for (int k = 0; k < 3; k++) {
                ull wA, wB;
                lds128p(cwt_a + (unsigned)k * 256, wA, wB);
                #pragma unroll
                for (int r = 0; r < 8; r++) {
                    acc[r][0] = ffma2(xd[r + k], wA, acc[r][0]);
                    acc[r][1] = ffma2(xd[r + k], wB, acc[r][1]);
                }
            }
            cwt_a += 768;
        }
    }

    #pragma unroll
    for (int r = 0; r < 8; r++) {
        float o0, o1, o2, o3;
        unpack2(acc[r][0], o0, o1);
        unpack2(acc[r][1], o2, o3);
        *(float4*)(g_h + ((size_t)b * Wn + w0 + wbase + r) * Fc + f0) =
            make_float4(o0, o1, o2, o3);
    }
}

// ---------------------------------------------------------------------------
// Kernel O (mma.sync tf32): 128w x 128d tile per CTA.
// A smem: [130 rows][64 f] stride 68 words (row j = h[(w0-1+j) mod Wn]).
// B smem: [128 d][192 kk] stride 196 words (kk = k*64+f, from g_twB).
// 3 passes (conv taps = A row-base shift), 8 k-steps of K=8 each.
// 16 warps: warp tile 32w x 32d = 2 m-tiles x 4 n-tiles of m16n8k8.
// ---------------------------------------------------------------------------
#define OM_A     0
#define OM_ASTR  68                       // words; 272 B; 68 % 32 == 4
#define OM_B     (130 * 272)              // 35360 B
#define OM_BSTR  196                      // words; 784 B; 196 % 32 == 4
#define OM_SMEM  (OM_B + 128 * 784)       // 135712 B

__global__ void __launch_bounds__(512, 1) out_mma_kernel(float* __restrict__ out)
{
    extern __shared__ char smc[];
    uint32_t sbase = smem_u32(smc);
    const int t   = threadIdx.x;
    const int wid = t >> 5;
    const int l   = t & 31;
    const int b   = blockIdx.y;
    const int w0  = blockIdx.x * 128;

    // ---- stage A (h rows, tf32) ----
    const float* hb = g_h + (size_t)b * Wn * Fc;
    for (int i = t; i < 130 * 64; i += 512) {
        int j = i >> 6, f = i & 63;
        int gw = (w0 - 1 + j + Wn) & (Wn - 1);
        *(uint32_t*)(smc + OM_A + (j * OM_ASTR + f) * 4) = cvt_tf32(hb[(size_t)gw * Fc + f]);
    }
    // ---- stage B (weights, tf32) ----
    for (int i = t; i < 128 * 192; i += 512) {
        int d = i / 192, kk = i - d * 192;
        *(uint32_t*)(smc + OM_B + (d * OM_BSTR + kk) * 4) = cvt_tf32(g_twB[i]);
    }
    __syncthreads();

    const int R = (wid & 3) * 32;          // warp w-base
    const int D = (wid >> 2) * 32;         // warp d-base

    // per-lane ldmatrix addresses
    const int a_row_in = (l & 7) + ((l >> 3) & 1) * 8;
    uint32_t aA = sbase + OM_A + (uint32_t)(R + a_row_in) * 272 + (uint32_t)(l >> 4) * 16;
    const int b_d_in = (l & 7) + (l >> 4) * 8;
    uint32_t aB = sbase + OM_B + (uint32_t)(D + b_d_in) * 784 + (uint32_t)((l >> 3) & 1) * 16;

    float acc[8][4];
    #pragma unroll
    for (int i = 0; i < 8; i++)
        #pragma unroll
        for (int j = 0; j < 4; j++) acc[i][j] = 0.f;

    #pragma unroll
    for (int pass = 0; pass < 3; pass++) {
        uint32_t a0base = aA + (uint32_t)pass * 272;       // conv tap = row shift
        uint32_t b0base = aB + (uint32_t)pass * 256;       // kk += 64 per pass
        #pragma unroll
        for (int s = 0; s < 8; s++) {
            uint32_t fa0[4], fa1[4], fb0[4], fb1[4];
            ldsm_x4(a0base + 32u * s, fa0);                // m-tile 0 (rows R..R+15)
            ldsm_x4(a0base + 16u * 272 + 32u * s, fa1);    // m-tile 1 (rows R+16..)
            ldsm_x4(b0base + 32u * s, fb0);                // n-tiles 0,1 (d D..D+15)
            ldsm_x4(b0base + 16u * 784 + 32u * s, fb1);    // n-tiles 2,3
            mma_tf32(acc[0], fa0, fb0[0], fb0[1]);
            mma_tf32(acc[1], fa0, fb0[2], fb0[3]);
            mma_tf32(acc[2], fa0, fb1[0], fb1[1]);
            mma_tf32(acc[3], fa0, fb1[2], fb1[3]);
            mma_tf32(acc[4], fa1, fb0[0], fb0[1]);
            mma_tf32(acc[5], fa1, fb0[2], fb0[3]);
            mma_tf32(acc[6], fa1, fb1[0], fb1[1]);
            mma_tf32(acc[7], fa1, fb1[2], fb1[3]);
        }
    }

    // ---- epilogue: C fragment -> gmem ----
    const int gr  = l >> 2;
    const int gc2 = (l & 3) * 2;
    #pragma unroll
    for (int mt = 0; mt < 2; mt++) {
        #pragma unroll
        for (int nt = 0; nt < 4; nt++) {
            const float* c = acc[mt * 4 + nt];
            int w_row = w0 + R + mt * 16 + gr;
            int d_col = D + nt * 8 + gc2;
            float* ob = out + ((size_t)b * Wn + w_row) * Dc + d_col;
            *(float2*)(ob)            = make_float2(c[0], c[1]);
            *(float2*)(ob + 8 * Dc)   = make_float2(c[2], c[3]);
        }
    }
}

// ---------------------------------------------------------------------------
extern "C" void kernel_launch(void* const* d_in, const int* in_sizes, int n_in,
                              void* d_out, int out_size) {
    const float* x       = (const float*)d_in[0];
    const float* ctx_w   = (const float*)d_in[1];
    const float* ctx_b   = (const float*)d_in[2];
    const float* token_w = (const float*)d_in[3];
    const float* seW_w   = (const float*)d_in[4];
    const float* seW_b   = (const float*)d_in[5];
    float* out = (float*)d_out;

    cudaFuncSetAttribute(h_kernel,
                         cudaFuncAttributeMaxDynamicSharedMemorySize, H_SMEM);
    cudaFuncSetAttribute(out_mma_kernel,
                         cudaFuncAttributeMaxDynamicSharedMemorySize, OM_SMEM);

    transpose_weights<<<48, 256>>>(ctx_w, token_w);
    gram_partial<<<dim3(GRAM_CHUNKS, Bc), 256>>>(x);
    gram_reduce<<<Bc, 256>>>();
    h_kernel<<<dim3(Wn / 256, Bc), 512, H_SMEM>>>(x, ctx_b, seW_w, seW_b);
    out_mma_kernel<<<dim3(Wn / 128, Bc), 512, OM_SMEM>>>(out);
}